// round 13
// baseline (speedup 1.0000x reference)
#include <cuda_runtime.h>
#include <cuda_fp16.h>
#include <cstdint>
#include <cstddef>

typedef unsigned long long ull;

#define T_LEN 2048
#define B_SZ  128
#define HID   64
#define G3    192
#define NCLS  20
#define VOCAB 50257
#define TPAD  (T_LEN + 32)

// per-vocab input projections WITH folded biases:
//   g_proj[v][d*192+g] = emb[v].wih_d[g] + bih_d[g] + (g<128 ? bhh_d[g] : 0)
__device__ float g_proj[(size_t)VOCAB * 384];
// pre-scaled, pre-reversed, padded token offsets: tok*384 + d*192
__device__ int g_tokoff[2 * B_SZ * TPAD];
// pooled features [b][256] = [mean_f, mean_b, max_f, max_b]
__device__ float g_feats[B_SZ * 256];

// ---------- packed f32x2 + fast-math helpers ----------
__device__ __forceinline__ void ffma2(ull& d, ull a, ull b) {
    asm("fma.rn.f32x2 %0, %1, %2, %0;" : "+l"(d) : "l"(a), "l"(b));
}
__device__ __forceinline__ void upk2(ull v, float& lo, float& hi) {
    asm("mov.b64 {%0, %1}, %2;" : "=f"(lo), "=f"(hi) : "l"(v));
}
__device__ __forceinline__ float tanha(float x) {
    float r; asm("tanh.approx.f32 %0, %1;" : "=f"(r) : "f"(x)); return r;
}
// sigmoid via single-MUFU tanh: sigma(x) = 0.5 + 0.5*tanh(x/2)
__device__ __forceinline__ float sigm_t(float p) {
    return fmaf(tanha(0.5f * p), 0.5f, 0.5f);
}

// =====================================================================
// Kernel T: token offset table. [d][b][t] = tokens[b][TIDX(t)]*384 + d*192
// =====================================================================
__global__ void kT(const int* __restrict__ tokens) {
    const int b = blockIdx.x, d = blockIdx.y;
    const int* src = tokens + b * T_LEN;
    int* dst = g_tokoff + (d * B_SZ + b) * TPAD;
    for (int t = threadIdx.x; t < TPAD; t += blockDim.x) {
        int tt = t < T_LEN ? t : T_LEN - 1;
        int idx = d ? (T_LEN - 1 - tt) : tt;
        dst[t] = src[idx] * 384 + d * 192;
    }
}

// =====================================================================
// Kernel A2: PROVEN round-8 version (two row-passes, ~102us).
// =====================================================================
__global__ void __launch_bounds__(256) kA2(
    const float* __restrict__ emb,
    const float* __restrict__ wih_f, const float* __restrict__ bih_f,
    const float* __restrict__ bhh_f,
    const float* __restrict__ wih_b, const float* __restrict__ bih_b,
    const float* __restrict__ bhh_b)
{
    __shared__ float2 xsh[64][32];   // [v_local][k2]
    __shared__ float2 wsh[32][97];   // [k2][g_local] padded
    __shared__ float  bsh[96];

    const int vt  = blockIdx.x;
    const int dg0 = blockIdx.y * 96;
    const int tid = threadIdx.x;

    for (int idx = tid; idx < 96 * 32; idx += 256) {
        int g = idx >> 5, k2 = idx & 31;
        int dg = dg0 + g;
        const float2* src = (dg < 192) ? (const float2*)(wih_f + dg * 64)
                                       : (const float2*)(wih_b + (dg - 192) * 64);
        wsh[k2][g] = src[k2];
    }
    if (tid < 96) {
        int dg = dg0 + tid;
        float bv;
        if (dg < 192) bv = bih_f[dg] + (dg < 128 ? bhh_f[dg] : 0.0f);
        else { int e = dg - 192; bv = bih_b[e] + (e < 128 ? bhh_b[e] : 0.0f); }
        bsh[tid] = bv;
    }
    for (int idx = tid; idx < 64 * 32; idx += 256) {
        int vl = idx >> 5, k2 = idx & 31;
        int v = vt * 64 + vl; if (v >= VOCAB) v = VOCAB - 1;
        xsh[vl][k2] = ((const float2*)(emb + (size_t)v * 64))[k2];
    }
    __syncthreads();

    const int lane = tid & 31;
    const int wrp  = tid >> 5;
    const ull* xp = (const ull*)xsh;
    const ull* wp = (const ull*)wsh;

#pragma unroll
    for (int pass = 0; pass < 2; pass++) {
        const int row0 = pass * 32 + wrp * 4;

        ull acc[4][3];
#pragma unroll
        for (int i = 0; i < 4; i++)
#pragma unroll
            for (int q = 0; q < 3; q++) acc[i][q] = 0ULL;

#pragma unroll 4
        for (int k2 = 0; k2 < 32; k2++) {
            ull xs[4], ws[3];
#pragma unroll
            for (int i = 0; i < 4; i++) xs[i] = xp[(row0 + i) * 32 + k2];
#pragma unroll
            for (int q = 0; q < 3; q++) ws[q] = wp[k2 * 97 + lane + 32 * q];
#pragma unroll
            for (int i = 0; i < 4; i++)
#pragma unroll
                for (int q = 0; q < 3; q++) ffma2(acc[i][q], xs[i], ws[q]);
        }

#pragma unroll
        for (int i = 0; i < 4; i++) {
            int v = vt * 64 + row0 + i;
            if (v < VOCAB) {
#pragma unroll
                for (int q = 0; q < 3; q++) {
                    int g = lane + 32 * q;
                    float lo, hi; upk2(acc[i][q], lo, hi);
                    g_proj[(size_t)v * 384 + dg0 + g] = lo + hi + bsh[g];
                }
            }
        }
    }
}

// =====================================================================
// Kernel B v13: full-row fp16 GRU recurrence, shuffle-free tail.
// 128 CTAs (1 per SM) = (direction, batch pair). 128 threads:
//   bb = tid>>6 (sequence), k = tid&63 (h unit).
// Each thread holds COMPLETE fp16 rows {k, 64+k, 128+k} of whh (96 half2
// regs) and computes full 64-length dots: 96 HFMA2/step, zero shuffles,
// fully local gating. h broadcast via 8x LDS.128 (consumed inline).
// 4-deep slot-resident gate pipeline; one __syncthreads per step.
// =====================================================================
__global__ void __launch_bounds__(128) kB(
    const float* __restrict__ whh_f, const float* __restrict__ bhh_f,
    const float* __restrict__ whh_b, const float* __restrict__ bhh_b)
{
    __shared__ __align__(16) __half h_sh[2][2][64];   // [buf][bb][k]

    const int tid = threadIdx.x;
    const int bb  = tid >> 6;
    const int k   = tid & 63;
    const int d   = blockIdx.x >> 6;
    const int bp  = blockIdx.x & 63;
    const int b   = bp * 2 + bb;

    const float* whh = d ? whh_b : whh_f;
    const float* bhh = d ? bhh_b : bhh_f;

    // full fp16 rows: 32 half2 per gate
    __half2 wr[32], wz[32], wn[32];
    {
        const float2* prp = (const float2*)(whh + (size_t)k * 64);
        const float2* pzp = (const float2*)(whh + (size_t)(64 + k) * 64);
        const float2* pnp = (const float2*)(whh + (size_t)(128 + k) * 64);
#pragma unroll
        for (int i = 0; i < 32; i++) {
            wr[i] = __float22half2_rn(prp[i]);
            wz[i] = __float22half2_rn(pzp[i]);
            wn[i] = __float22half2_rn(pnp[i]);
        }
    }
    const float bn = bhh[128 + k];

    h_sh[0][bb][k] = __float2half(0.0f);

    const int4* tq = (const int4*)(g_tokoff + (d * B_SZ + b) * TPAD);
    const float* pR = g_proj + k;        // xr + bih_r + bhh_r
    const float* pZ = g_proj + 64 + k;   // xz + bih_z + bhh_z
    const float* pN = g_proj + 128 + k;  // xn + bih_n

    // 4-deep pipeline; q1 holds offsets for steps [t0+4, t0+8)
    int4 q0 = tq[0], q1 = tq[1];
    float bufR[4], bufZ[4], bufN[4];
    bufR[0] = pR[q0.x]; bufZ[0] = pZ[q0.x]; bufN[0] = pN[q0.x];
    bufR[1] = pR[q0.y]; bufZ[1] = pZ[q0.y]; bufN[1] = pN[q0.y];
    bufR[2] = pR[q0.z]; bufZ[2] = pZ[q0.z]; bufN[2] = pN[q0.z];
    bufR[3] = pR[q0.w]; bufZ[3] = pZ[q0.w]; bufN[3] = pN[q0.w];

    float hprev = 0.0f, sum = 0.0f, mx = -1e30f;
    __syncthreads();

    const __half2 z2 = __float2half2_rn(0.0f);

    for (int t0 = 0; t0 < T_LEN; t0 += 4) {
        int4 qn;
#pragma unroll
        for (int j = 0; j < 4; j++) {
            const int cur = j & 1;          // t0 multiple of 4 -> (t&1)==(j&1)

            const float aR = bufR[j], aZ = bufZ[j], aN = bufN[j];
            if (j == 0) qn = tq[(t0 + 8) >> 2];
            {
                const int voj = (j == 0) ? q1.x : (j == 1) ? q1.y :
                                (j == 2) ? q1.z : q1.w;
                bufR[j] = pR[voj]; bufZ[j] = pZ[voj]; bufN[j] = pN[voj];
            }

            // full dot: 8 blocks x (LDS.128 = 4 half2) x 3 gates
            const uint4* hp = (const uint4*)&h_sh[cur][bb][0];
            __half2 ar0 = z2, ar1 = z2, az0 = z2, az1 = z2, an0 = z2, an1 = z2;
#pragma unroll
            for (int blk = 0; blk < 8; blk++) {
                uint4 u = hp[blk];
                __half2 h0 = *(__half2*)&u.x, h1 = *(__half2*)&u.y;
                __half2 h2 = *(__half2*)&u.z, h3 = *(__half2*)&u.w;
                ar0 = __hfma2(wr[4 * blk], h0, ar0);
                ar1 = __hfma2(wr[4 * blk + 1], h1, ar1);
                ar0 = __hfma2(wr[4 * blk + 2], h2, ar0);
                ar1 = __hfma2(wr[4 * blk + 3], h3, ar1);
                az0 = __hfma2(wz[4 * blk], h0, az0);
                az1 = __hfma2(wz[4 * blk + 1], h1, az1);
                az0 = __hfma2(wz[4 * blk + 2], h2, az0);
                az1 = __hfma2(wz[4 * blk + 3], h3, az1);
                an0 = __hfma2(wn[4 * blk], h0, an0);
                an1 = __hfma2(wn[4 * blk + 1], h1, an1);
                an0 = __hfma2(wn[4 * blk + 2], h2, an0);
                an1 = __hfma2(wn[4 * blk + 3], h3, an1);
            }
            // fp32 combine (proven pattern)
            float2 fr0 = __half22float2(ar0), fr1 = __half22float2(ar1);
            float2 fz0 = __half22float2(az0), fz1 = __half22float2(az1);
            float2 fn0 = __half22float2(an0), fn1 = __half22float2(an1);
            const float pr = (fr0.x + fr0.y) + (fr1.x + fr1.y);
            const float pz = (fz0.x + fz0.y) + (fz1.x + fz1.y);
            const float pn = (fn0.x + fn0.y) + (fn1.x + fn1.y);

            // fully local gating (no shuffles)
            const float R  = sigm_t(pr + aR);
            const float Z  = sigm_t(pz + aZ);
            const float N  = tanha(fmaf(R, pn + bn, aN));
            const float hn = fmaf(Z, hprev - N, N);     // (1-z)n + z h
            hprev = hn;
            h_sh[cur ^ 1][bb][k] = __float2half(hn);
            sum += hn;
            mx = fmaxf(mx, hn);

            __syncthreads();
        }
        q1 = qn;
    }

    float* f = g_feats + b * 256;
    if (d == 0) { f[k]      = sum * (1.0f / T_LEN); f[128 + k] = mx; }
    else        { f[64 + k] = sum * (1.0f / T_LEN); f[192 + k] = mx; }
}

// =====================================================================
// Kernel C v2: classifier head, 256 threads per batch row.
// =====================================================================
__global__ void __launch_bounds__(256) kC(
    const float* __restrict__ w1, const float* __restrict__ b1,
    const float* __restrict__ w2, const float* __restrict__ b2,
    float* __restrict__ out)
{
    const int b   = blockIdx.x;
    const int tid = threadIdx.x;
    __shared__ float hid[64];

    {
        const int j = tid >> 2, q = tid & 3;
        const float4* f4 = (const float4*)(g_feats + b * 256 + q * 64);
        const float4* w4 = (const float4*)(w1 + j * 256 + q * 64);
        float a0 = 0.f, a1 = 0.f, a2 = 0.f, a3 = 0.f;
#pragma unroll
        for (int i = 0; i < 16; i += 4) {
            float4 fa = f4[i],     wa = w4[i];
            float4 fb = f4[i + 1], wb = w4[i + 1];
            float4 fc = f4[i + 2], wc = w4[i + 2];
            float4 fd = f4[i + 3], wd = w4[i + 3];
            a0 += fa.x * wa.x + fa.y * wa.y + fa.z * wa.z + fa.w * wa.w;
            a1 += fb.x * wb.x + fb.y * wb.y + fb.z * wb.z + fb.w * wb.w;
            a2 += fc.x * wc.x + fc.y * wc.y + fc.z * wc.z + fc.w * wc.w;
            a3 += fd.x * wd.x + fd.y * wd.y + fd.z * wd.z + fd.w * wd.w;
        }
        float acc = (a0 + a1) + (a2 + a3);
        acc += __shfl_xor_sync(0xffffffffu, acc, 1);
        acc += __shfl_xor_sync(0xffffffffu, acc, 2);
        if (q == 0) {
            acc += b1[j];
            hid[j] = 0.5f * acc * (1.0f + erff(acc * 0.70710678118654752f));
        }
    }
    __syncthreads();

    if (tid < NCLS * 8) {
        const int c = tid >> 3, i8 = tid & 7;
        const float* w2r = w2 + c * 64 + i8 * 8;
        const float* hp  = hid + i8 * 8;
        float o = 0.f;
#pragma unroll
        for (int i = 0; i < 8; i++) o += hp[i] * w2r[i];
        o += __shfl_xor_sync(0xffffffffu, o, 1);
        o += __shfl_xor_sync(0xffffffffu, o, 2);
        o += __shfl_xor_sync(0xffffffffu, o, 4);
        if (i8 == 0) out[b * NCLS + c] = o + b2[c];
    }
}

// =====================================================================
extern "C" void kernel_launch(void* const* d_in, const int* in_sizes, int n_in,
                              void* d_out, int out_size)
{
    const int*   tokens = (const int*)  d_in[0];
    const float* emb    = (const float*)d_in[1];
    const float* wih_f  = (const float*)d_in[2];
    const float* whh_f  = (const float*)d_in[3];
    const float* bih_f  = (const float*)d_in[4];
    const float* bhh_f  = (const float*)d_in[5];
    const float* wih_b  = (const float*)d_in[6];
    const float* whh_b  = (const float*)d_in[7];
    const float* bih_b  = (const float*)d_in[8];
    const float* bhh_b  = (const float*)d_in[9];
    const float* w1     = (const float*)d_in[10];
    const float* b1     = (const float*)d_in[11];
    const float* w2     = (const float*)d_in[12];
    const float* b2     = (const float*)d_in[13];
    float* out = (float*)d_out;

    kT<<<dim3(B_SZ, 2), 256>>>(tokens);
    const int vtiles = (VOCAB + 63) / 64;   // 786
    kA2<<<dim3(vtiles, 4), 256>>>(emb, wih_f, bih_f, bhh_f, wih_b, bih_b, bhh_b);
    kB<<<128, 128>>>(whh_f, bhh_f, whh_b, bhh_b);
    kC<<<128, 256>>>(w1, b1, w2, b2, out);
}

// round 14
// speedup vs baseline: 1.0541x; 1.0541x over previous
#include <cuda_runtime.h>
#include <cuda_fp16.h>
#include <cstdint>
#include <cstddef>

typedef unsigned long long ull;

#define T_LEN 2048
#define B_SZ  128
#define HID   64
#define G3    192
#define NCLS  20
#define VOCAB 50257
#define TPAD  (T_LEN + 32)

// per-vocab input projections WITH folded biases:
//   g_proj[v][d*192+g] = emb[v].wih_d[g] + bih_d[g] + (g<128 ? bhh_d[g] : 0)
__device__ float g_proj[(size_t)VOCAB * 384];
// pre-scaled, pre-reversed, padded token offsets: tok*384 + d*192
__device__ int g_tokoff[2 * B_SZ * TPAD];
// pooled features [b][256] = [mean_f, mean_b, max_f, max_b]
__device__ float g_feats[B_SZ * 256];

// ---------- fast-math helpers ----------
__device__ __forceinline__ float tanha(float x) {
    float r; asm("tanh.approx.f32 %0, %1;" : "=f"(r) : "f"(x)); return r;
}
// sigmoid via single-MUFU tanh: sigma(x) = 0.5 + 0.5*tanh(x/2)
__device__ __forceinline__ float sigm_t(float p) {
    return fmaf(tanha(0.5f * p), 0.5f, 0.5f);
}

// =====================================================================
// Kernel T: token offset table. [d][b][t] = tokens[b][TIDX(t)]*384 + d*192
// =====================================================================
__global__ void kT(const int* __restrict__ tokens) {
    const int b = blockIdx.x, d = blockIdx.y;
    const int* src = tokens + b * T_LEN;
    int* dst = g_tokoff + (d * B_SZ + b) * TPAD;
    for (int t = threadIdx.x; t < TPAD; t += blockDim.x) {
        int tt = t < T_LEN ? t : T_LEN - 1;
        int idx = d ? (T_LEN - 1 - tt) : tt;
        dst[t] = src[idx] * 384 + d * 192;
    }
}

// =====================================================================
// Kernel A2 v7: vocab projection table in fp16 HFMA2.
// Identical structure to the proven round-8 version, but x/w staged as
// half2 and the 12 inner FMAs are HFMA2 (rt=2 vs f32x2's rt=3 -> 1.5x
// on the binding issue rate, confirmed by fma=32.8%~=1/3 saturation).
// Two 16-deep fp16 chains per output (k2 parity), fp32 combine.
// smem 20.5KB + ~60 regs -> 4 CTAs/SM (was 2).
// =====================================================================
__global__ void __launch_bounds__(256) kA2(
    const float* __restrict__ emb,
    const float* __restrict__ wih_f, const float* __restrict__ bih_f,
    const float* __restrict__ bhh_f,
    const float* __restrict__ wih_b, const float* __restrict__ bih_b,
    const float* __restrict__ bhh_b)
{
    __shared__ __half2 xsh[64][32];   // [v_local][k2]  (8 KB)
    __shared__ __half2 wsh[32][97];   // [k2][g_local] padded (12.1 KB)
    __shared__ float   bsh[96];

    const int vt  = blockIdx.x;
    const int dg0 = blockIdx.y * 96;
    const int tid = threadIdx.x;

    // stage weights as half2: wsh[k2][g] = (w[dg][2k2], w[dg][2k2+1])
    for (int idx = tid; idx < 96 * 32; idx += 256) {
        int g = idx >> 5, k2 = idx & 31;
        int dg = dg0 + g;
        const float2* src = (dg < 192) ? (const float2*)(wih_f + dg * 64)
                                       : (const float2*)(wih_b + (dg - 192) * 64);
        wsh[k2][g] = __float22half2_rn(src[k2]);
    }
    if (tid < 96) {
        int dg = dg0 + tid;
        float bv;
        if (dg < 192) bv = bih_f[dg] + (dg < 128 ? bhh_f[dg] : 0.0f);
        else { int e = dg - 192; bv = bih_b[e] + (e < 128 ? bhh_b[e] : 0.0f); }
        bsh[tid] = bv;
    }
    // stage embeddings as half2
    for (int idx = tid; idx < 64 * 32; idx += 256) {
        int vl = idx >> 5, k2 = idx & 31;
        int v = vt * 64 + vl; if (v >= VOCAB) v = VOCAB - 1;
        xsh[vl][k2] = __float22half2_rn(((const float2*)(emb + (size_t)v * 64))[k2]);
    }
    __syncthreads();

    const int lane = tid & 31;
    const int wrp  = tid >> 5;
    const __half2 z2 = __float2half2_rn(0.0f);

#pragma unroll
    for (int pass = 0; pass < 2; pass++) {
        const int row0 = pass * 32 + wrp * 4;

        // two fp16 chains per output (k2 parity), 16 deep each
        __half2 acc[4][3][2];
#pragma unroll
        for (int i = 0; i < 4; i++)
#pragma unroll
            for (int q = 0; q < 3; q++) { acc[i][q][0] = z2; acc[i][q][1] = z2; }

#pragma unroll 4
        for (int k2 = 0; k2 < 32; k2++) {
            const int c = k2 & 1;
            __half2 xs[4], ws[3];
#pragma unroll
            for (int i = 0; i < 4; i++) xs[i] = xsh[row0 + i][k2];   // broadcast
#pragma unroll
            for (int q = 0; q < 3; q++) ws[q] = wsh[k2][lane + 32 * q]; // coalesced
#pragma unroll
            for (int i = 0; i < 4; i++)
#pragma unroll
                for (int q = 0; q < 3; q++)
                    acc[i][q][c] = __hfma2(xs[i], ws[q], acc[i][q][c]);
        }

#pragma unroll
        for (int i = 0; i < 4; i++) {
            int v = vt * 64 + row0 + i;
            if (v < VOCAB) {
#pragma unroll
                for (int q = 0; q < 3; q++) {
                    int g = lane + 32 * q;
                    // fp32 combine of the two fp16 chains
                    float2 c0 = __half22float2(acc[i][q][0]);
                    float2 c1 = __half22float2(acc[i][q][1]);
                    g_proj[(size_t)v * 384 + dg0 + g] =
                        (c0.x + c0.y) + (c1.x + c1.y) + bsh[g];
                }
            }
        }
    }
}

// =====================================================================
// Kernel B v10 (FROZEN, proven): fp16 HFMA2 recurrent dot, fp32
// chain-combine. 256 CTAs = one (d,b) sequence, 128 threads:
// k = tid>>1, half = tid&1. 8-deep slot pipeline, 1 bar/step.
// =====================================================================
__global__ void __launch_bounds__(128) kB(
    const float* __restrict__ whh_f, const float* __restrict__ bhh_f,
    const float* __restrict__ whh_b, const float* __restrict__ bhh_b)
{
    __shared__ __align__(16) __half h_sh[2][64];   // [buf][k]

    const int tid  = threadIdx.x;
    const int k    = tid >> 1;
    const int half = tid & 1;
    const int d    = blockIdx.x >> 7;
    const int b    = blockIdx.x & 127;

    const float* whh = d ? whh_b : whh_f;
    const float* bhh = d ? bhh_b : bhh_f;

    // fp16x2 register-resident weight halves (cols [half*32, half*32+32))
    __half2 wr[16], wz[16], wn[16];
    {
        const float2* prp = (const float2*)(whh + (size_t)k * 64         + half * 32);
        const float2* pzp = (const float2*)(whh + (size_t)(64 + k) * 64  + half * 32);
        const float2* pnp = (const float2*)(whh + (size_t)(128 + k) * 64 + half * 32);
#pragma unroll
        for (int i = 0; i < 16; i++) {
            wr[i] = __float22half2_rn(prp[i]);
            wz[i] = __float22half2_rn(pzp[i]);
            wn[i] = __float22half2_rn(pnp[i]);
        }
    }
    const float bn = bhh[128 + k];

    if (tid < 64) h_sh[0][tid] = __float2half(0.0f);

    const int4* tq = (const int4*)(g_tokoff + (d * B_SZ + b) * TPAD);
    const float* pA = g_proj + (half ? 64 : 0) + k;  // xr (half0) / xz (half1)
    const float* pB = g_proj + 128 + k;              // xn (both halves)

    int4 q0 = tq[0], q1 = tq[1], q2 = tq[2], q3 = tq[3];

    float bufA[8], bufB[8];
    bufA[0] = pA[q0.x]; bufB[0] = pB[q0.x];
    bufA[1] = pA[q0.y]; bufB[1] = pB[q0.y];
    bufA[2] = pA[q0.z]; bufB[2] = pB[q0.z];
    bufA[3] = pA[q0.w]; bufB[3] = pB[q0.w];
    bufA[4] = pA[q1.x]; bufB[4] = pB[q1.x];
    bufA[5] = pA[q1.y]; bufB[5] = pB[q1.y];
    bufA[6] = pA[q1.z]; bufB[6] = pB[q1.z];
    bufA[7] = pA[q1.w]; bufB[7] = pB[q1.w];

    float hprev = 0.0f, sum = 0.0f, mx = -1e30f;
    __syncthreads();

    const __half2 z2 = __float2half2_rn(0.0f);

    for (int t0 = 0; t0 < T_LEN; t0 += 8) {
        int4 qn0, qn1;
#pragma unroll
        for (int j = 0; j < 8; j++) {
            const int cur = j & 1;

            const float a0 = bufA[j];       // xr+b (half0) / xz+b (half1)
            const float b0 = bufB[j];       // xn+bih_n
            if (j == 0) qn0 = tq[(t0 + 16) >> 2];
            if (j == 4) qn1 = tq[(t0 + 20) >> 2];
            {
                const int voj = (j == 0) ? q2.x : (j == 1) ? q2.y : (j == 2) ? q2.z :
                                (j == 3) ? q2.w : (j == 4) ? q3.x : (j == 5) ? q3.y :
                                (j == 6) ? q3.z : q3.w;
                bufA[j] = pA[voj];
                bufB[j] = pB[voj];
            }

            // load 32 h halves (this thread's column slice) = 16 half2
            __half2 hv[16];
            {
                const uint4* hp = (const uint4*)&h_sh[cur][half * 32];
                uint4 u0 = hp[0], u1 = hp[1], u2 = hp[2], u3 = hp[3];
                ((uint4*)hv)[0] = u0; ((uint4*)hv)[1] = u1;
                ((uint4*)hv)[2] = u2; ((uint4*)hv)[3] = u3;
            }

            // fp16 half-dot: 2 accumulation chains per gate row
            __half2 ar0 = z2, ar1 = z2, az0 = z2, az1 = z2, an0 = z2, an1 = z2;
#pragma unroll
            for (int i = 0; i < 8; i++) {
                ar0 = __hfma2(wr[2 * i], hv[2 * i], ar0);
                ar1 = __hfma2(wr[2 * i + 1], hv[2 * i + 1], ar1);
                az0 = __hfma2(wz[2 * i], hv[2 * i], az0);
                az1 = __hfma2(wz[2 * i + 1], hv[2 * i + 1], az1);
                an0 = __hfma2(wn[2 * i], hv[2 * i], an0);
                an1 = __hfma2(wn[2 * i + 1], hv[2 * i + 1], an1);
            }
            // fp32 finish: unpack both halves of both chains, sum in fp32
            float2 fr0 = __half22float2(ar0), fr1 = __half22float2(ar1);
            float2 fz0 = __half22float2(az0), fz1 = __half22float2(az1);
            float2 fn0 = __half22float2(an0), fn1 = __half22float2(an1);
            float pr = (fr0.x + fr0.y) + (fr1.x + fr1.y);
            float pz = (fz0.x + fz0.y) + (fz1.x + fz1.y);
            float pn = (fn0.x + fn0.y) + (fn1.x + fn1.y);

            pr += (half == 0) ? a0 : 0.0f;
            pz += (half == 1) ? a0 : 0.0f;
            pn += (half == 0) ? bn : 0.0f;
            pr += __shfl_xor_sync(0xffffffffu, pr, 1);
            pz += __shfl_xor_sync(0xffffffffu, pz, 1);
            pn += __shfl_xor_sync(0xffffffffu, pn, 1);

            const float R  = sigm_t(pr);
            const float Z  = sigm_t(pz);
            const float N  = tanha(fmaf(R, pn, b0));
            const float hn = fmaf(Z, hprev - N, N);     // (1-z)n + z h
            hprev = hn;
            if (half == 0) h_sh[cur ^ 1][k] = __float2half(hn);
            sum += hn;
            mx = fmaxf(mx, hn);

            __syncthreads();
        }
        q2 = qn0; q3 = qn1;
    }

    if (half == 0) {
        float* f = g_feats + b * 256;
        if (d == 0) { f[k]      = sum * (1.0f / T_LEN); f[128 + k] = mx; }
        else        { f[64 + k] = sum * (1.0f / T_LEN); f[192 + k] = mx; }
    }
}

// =====================================================================
// Kernel C v2: classifier head, 256 threads per batch row.
// =====================================================================
__global__ void __launch_bounds__(256) kC(
    const float* __restrict__ w1, const float* __restrict__ b1,
    const float* __restrict__ w2, const float* __restrict__ b2,
    float* __restrict__ out)
{
    const int b   = blockIdx.x;
    const int tid = threadIdx.x;
    __shared__ float hid[64];

    {
        const int j = tid >> 2, q = tid & 3;
        const float4* f4 = (const float4*)(g_feats + b * 256 + q * 64);
        const float4* w4 = (const float4*)(w1 + j * 256 + q * 64);
        float a0 = 0.f, a1 = 0.f, a2 = 0.f, a3 = 0.f;
#pragma unroll
        for (int i = 0; i < 16; i += 4) {
            float4 fa = f4[i],     wa = w4[i];
            float4 fb = f4[i + 1], wb = w4[i + 1];
            float4 fc = f4[i + 2], wc = w4[i + 2];
            float4 fd = f4[i + 3], wd = w4[i + 3];
            a0 += fa.x * wa.x + fa.y * wa.y + fa.z * wa.z + fa.w * wa.w;
            a1 += fb.x * wb.x + fb.y * wb.y + fb.z * wb.z + fb.w * wb.w;
            a2 += fc.x * wc.x + fc.y * wc.y + fc.z * wc.z + fc.w * wc.w;
            a3 += fd.x * wd.x + fd.y * wd.y + fd.z * wd.z + fd.w * wd.w;
        }
        float acc = (a0 + a1) + (a2 + a3);
        acc += __shfl_xor_sync(0xffffffffu, acc, 1);
        acc += __shfl_xor_sync(0xffffffffu, acc, 2);
        if (q == 0) {
            acc += b1[j];
            hid[j] = 0.5f * acc * (1.0f + erff(acc * 0.70710678118654752f));
        }
    }
    __syncthreads();

    if (tid < NCLS * 8) {
        const int c = tid >> 3, i8 = tid & 7;
        const float* w2r = w2 + c * 64 + i8 * 8;
        const float* hp  = hid + i8 * 8;
        float o = 0.f;
#pragma unroll
        for (int i = 0; i < 8; i++) o += hp[i] * w2r[i];
        o += __shfl_xor_sync(0xffffffffu, o, 1);
        o += __shfl_xor_sync(0xffffffffu, o, 2);
        o += __shfl_xor_sync(0xffffffffu, o, 4);
        if (i8 == 0) out[b * NCLS + c] = o + b2[c];
    }
}

// =====================================================================
extern "C" void kernel_launch(void* const* d_in, const int* in_sizes, int n_in,
                              void* d_out, int out_size)
{
    const int*   tokens = (const int*)  d_in[0];
    const float* emb    = (const float*)d_in[1];
    const float* wih_f  = (const float*)d_in[2];
    const float* whh_f  = (const float*)d_in[3];
    const float* bih_f  = (const float*)d_in[4];
    const float* bhh_f  = (const float*)d_in[5];
    const float* wih_b  = (const float*)d_in[6];
    const float* whh_b  = (const float*)d_in[7];
    const float* bih_b  = (const float*)d_in[8];
    const float* bhh_b  = (const float*)d_in[9];
    const float* w1     = (const float*)d_in[10];
    const float* b1     = (const float*)d_in[11];
    const float* w2     = (const float*)d_in[12];
    const float* b2     = (const float*)d_in[13];
    float* out = (float*)d_out;

    kT<<<dim3(B_SZ, 2), 256>>>(tokens);
    const int vtiles = (VOCAB + 63) / 64;   // 786
    kA2<<<dim3(vtiles, 4), 256>>>(emb, wih_f, bih_f, bhh_f, wih_b, bih_b, bhh_b);
    kB<<<256, 128>>>(whh_f, bhh_f, whh_b, bhh_b);
    kC<<<128, 256>>>(w1, b1, w2, b2, out);
}

// round 15
// speedup vs baseline: 1.1310x; 1.0729x over previous
#include <cuda_runtime.h>
#include <cuda_fp16.h>
#include <cstdint>
#include <cstddef>

typedef unsigned long long ull;

#define T_LEN 2048
#define B_SZ  128
#define HID   64
#define G3    192
#define NCLS  20
#define VOCAB 50257
#define TPAD  (T_LEN + 32)

// per-vocab input projections WITH folded biases:
//   g_proj[v][d*192+g] = emb[v].wih_d[g] + bih_d[g] + (g<128 ? bhh_d[g] : 0)
__device__ float g_proj[(size_t)VOCAB * 384];
// pre-scaled, pre-reversed, padded token offsets: tok*384 + d*192
__device__ int g_tokoff[2 * B_SZ * TPAD];
// pooled features [b][256] = [mean_f, mean_b, max_f, max_b]
__device__ float g_feats[B_SZ * 256];

// ---------- fast-math helpers ----------
__device__ __forceinline__ float tanha(float x) {
    float r; asm("tanh.approx.f32 %0, %1;" : "=f"(r) : "f"(x)); return r;
}
// sigmoid via single-MUFU tanh: sigma(x) = 0.5 + 0.5*tanh(x/2)
__device__ __forceinline__ float sigm_t(float p) {
    return fmaf(tanha(0.5f * p), 0.5f, 0.5f);
}

// =====================================================================
// Kernel T: token offset table. [d][b][t] = tokens[b][TIDX(t)]*384 + d*192
// =====================================================================
__global__ void kT(const int* __restrict__ tokens) {
    const int b = blockIdx.x, d = blockIdx.y;
    const int* src = tokens + b * T_LEN;
    int* dst = g_tokoff + (d * B_SZ + b) * TPAD;
    for (int t = threadIdx.x; t < TPAD; t += blockDim.x) {
        int tt = t < T_LEN ? t : T_LEN - 1;
        int idx = d ? (T_LEN - 1 - tt) : tt;
        dst[t] = src[idx] * 384 + d * 192;
    }
}

// =====================================================================
// Kernel A2 v7 (FROZEN, proven r14): fp16 HFMA2 vocab projection.
// =====================================================================
__global__ void __launch_bounds__(256) kA2(
    const float* __restrict__ emb,
    const float* __restrict__ wih_f, const float* __restrict__ bih_f,
    const float* __restrict__ bhh_f,
    const float* __restrict__ wih_b, const float* __restrict__ bih_b,
    const float* __restrict__ bhh_b)
{
    __shared__ __half2 xsh[64][32];   // [v_local][k2]  (8 KB)
    __shared__ __half2 wsh[32][97];   // [k2][g_local] padded (12.1 KB)
    __shared__ float   bsh[96];

    const int vt  = blockIdx.x;
    const int dg0 = blockIdx.y * 96;
    const int tid = threadIdx.x;

    for (int idx = tid; idx < 96 * 32; idx += 256) {
        int g = idx >> 5, k2 = idx & 31;
        int dg = dg0 + g;
        const float2* src = (dg < 192) ? (const float2*)(wih_f + dg * 64)
                                       : (const float2*)(wih_b + (dg - 192) * 64);
        wsh[k2][g] = __float22half2_rn(src[k2]);
    }
    if (tid < 96) {
        int dg = dg0 + tid;
        float bv;
        if (dg < 192) bv = bih_f[dg] + (dg < 128 ? bhh_f[dg] : 0.0f);
        else { int e = dg - 192; bv = bih_b[e] + (e < 128 ? bhh_b[e] : 0.0f); }
        bsh[tid] = bv;
    }
    for (int idx = tid; idx < 64 * 32; idx += 256) {
        int vl = idx >> 5, k2 = idx & 31;
        int v = vt * 64 + vl; if (v >= VOCAB) v = VOCAB - 1;
        xsh[vl][k2] = __float22half2_rn(((const float2*)(emb + (size_t)v * 64))[k2]);
    }
    __syncthreads();

    const int lane = tid & 31;
    const int wrp  = tid >> 5;
    const __half2 z2 = __float2half2_rn(0.0f);

#pragma unroll
    for (int pass = 0; pass < 2; pass++) {
        const int row0 = pass * 32 + wrp * 4;

        __half2 acc[4][3][2];
#pragma unroll
        for (int i = 0; i < 4; i++)
#pragma unroll
            for (int q = 0; q < 3; q++) { acc[i][q][0] = z2; acc[i][q][1] = z2; }

#pragma unroll 4
        for (int k2 = 0; k2 < 32; k2++) {
            const int c = k2 & 1;
            __half2 xs[4], ws[3];
#pragma unroll
            for (int i = 0; i < 4; i++) xs[i] = xsh[row0 + i][k2];
#pragma unroll
            for (int q = 0; q < 3; q++) ws[q] = wsh[k2][lane + 32 * q];
#pragma unroll
            for (int i = 0; i < 4; i++)
#pragma unroll
                for (int q = 0; q < 3; q++)
                    acc[i][q][c] = __hfma2(xs[i], ws[q], acc[i][q][c]);
        }

#pragma unroll
        for (int i = 0; i < 4; i++) {
            int v = vt * 64 + row0 + i;
            if (v < VOCAB) {
#pragma unroll
                for (int q = 0; q < 3; q++) {
                    int g = lane + 32 * q;
                    float2 c0 = __half22float2(acc[i][q][0]);
                    float2 c1 = __half22float2(acc[i][q][1]);
                    g_proj[(size_t)v * 384 + dg0 + g] =
                        (c0.x + c0.y) + (c1.x + c1.y) + bsh[g];
                }
            }
        }
    }
}

// =====================================================================
// Kernel B v14: v10 structure + hadd2 chain-combine (proven safe r12)
// + symmetric 0.5*bn fold (removes predicated selects from the chain).
// 256 CTAs = one (d,b) sequence, 128 threads: k = tid>>1, half = tid&1.
// =====================================================================
__global__ void __launch_bounds__(128) kB(
    const float* __restrict__ whh_f, const float* __restrict__ bhh_f,
    const float* __restrict__ whh_b, const float* __restrict__ bhh_b)
{
    __shared__ __align__(16) __half h_sh[2][64];   // [buf][k]

    const int tid  = threadIdx.x;
    const int k    = tid >> 1;
    const int half = tid & 1;
    const int d    = blockIdx.x >> 7;
    const int b    = blockIdx.x & 127;

    const float* whh = d ? whh_b : whh_f;
    const float* bhh = d ? bhh_b : bhh_f;

    // fp16x2 register-resident weight halves (cols [half*32, half*32+32))
    __half2 wr[16], wz[16], wn[16];
    {
        const float2* prp = (const float2*)(whh + (size_t)k * 64         + half * 32);
        const float2* pzp = (const float2*)(whh + (size_t)(64 + k) * 64  + half * 32);
        const float2* pnp = (const float2*)(whh + (size_t)(128 + k) * 64 + half * 32);
#pragma unroll
        for (int i = 0; i < 16; i++) {
            wr[i] = __float22half2_rn(prp[i]);
            wz[i] = __float22half2_rn(pzp[i]);
            wn[i] = __float22half2_rn(pnp[i]);
        }
    }
    const float bn_half = 0.5f * bhh[128 + k];   // symmetric fold, no select

    if (tid < 64) h_sh[0][tid] = __float2half(0.0f);

    const int4* tq = (const int4*)(g_tokoff + (d * B_SZ + b) * TPAD);
    const float* pA = g_proj + (half ? 64 : 0) + k;  // xr (half0) / xz (half1)
    const float* pB = g_proj + 128 + k;              // xn (both halves)

    int4 q0 = tq[0], q1 = tq[1], q2 = tq[2], q3 = tq[3];

    float bufA[8], bufB[8];
    bufA[0] = pA[q0.x]; bufB[0] = pB[q0.x];
    bufA[1] = pA[q0.y]; bufB[1] = pB[q0.y];
    bufA[2] = pA[q0.z]; bufB[2] = pB[q0.z];
    bufA[3] = pA[q0.w]; bufB[3] = pB[q0.w];
    bufA[4] = pA[q1.x]; bufB[4] = pB[q1.x];
    bufA[5] = pA[q1.y]; bufB[5] = pB[q1.y];
    bufA[6] = pA[q1.z]; bufB[6] = pB[q1.z];
    bufA[7] = pA[q1.w]; bufB[7] = pB[q1.w];

    float hprev = 0.0f, sum = 0.0f, mx = -1e30f;
    __syncthreads();

    const __half2 z2 = __float2half2_rn(0.0f);

    for (int t0 = 0; t0 < T_LEN; t0 += 8) {
        int4 qn0, qn1;
#pragma unroll
        for (int j = 0; j < 8; j++) {
            const int cur = j & 1;

            const float a0 = bufA[j];       // xr+b (half0) / xz+b (half1)
            const float b0 = bufB[j];       // xn+bih_n
            if (j == 0) qn0 = tq[(t0 + 16) >> 2];
            if (j == 4) qn1 = tq[(t0 + 20) >> 2];
            {
                const int voj = (j == 0) ? q2.x : (j == 1) ? q2.y : (j == 2) ? q2.z :
                                (j == 3) ? q2.w : (j == 4) ? q3.x : (j == 5) ? q3.y :
                                (j == 6) ? q3.z : q3.w;
                bufA[j] = pA[voj];
                bufB[j] = pB[voj];
            }

            // load 32 h halves (this thread's column slice) = 16 half2
            __half2 hv[16];
            {
                const uint4* hp = (const uint4*)&h_sh[cur][half * 32];
                uint4 u0 = hp[0], u1 = hp[1], u2 = hp[2], u3 = hp[3];
                ((uint4*)hv)[0] = u0; ((uint4*)hv)[1] = u1;
                ((uint4*)hv)[2] = u2; ((uint4*)hv)[3] = u3;
            }

            // fp16 half-dot: 2 accumulation chains per gate row
            __half2 ar0 = z2, ar1 = z2, az0 = z2, az1 = z2, an0 = z2, an1 = z2;
#pragma unroll
            for (int i = 0; i < 8; i++) {
                ar0 = __hfma2(wr[2 * i], hv[2 * i], ar0);
                ar1 = __hfma2(wr[2 * i + 1], hv[2 * i + 1], ar1);
                az0 = __hfma2(wz[2 * i], hv[2 * i], az0);
                az1 = __hfma2(wz[2 * i + 1], hv[2 * i + 1], az1);
                an0 = __hfma2(wn[2 * i], hv[2 * i], an0);
                an1 = __hfma2(wn[2 * i + 1], hv[2 * i + 1], an1);
            }
            // hadd2 combine (proven r12) + fp32 finish
            float2 fr = __half22float2(__hadd2(ar0, ar1));
            float2 fz = __half22float2(__hadd2(az0, az1));
            float2 fn = __half22float2(__hadd2(an0, an1));
            // fold the owned gate input + symmetric half-bias pre-shuffle:
            // half0 contributes a0 (=xr+biases) to pr; half1 contributes to pz.
            float pr = fr.x + fr.y + (half ? 0.0f : a0);
            float pz = fz.x + fz.y + (half ? a0 : 0.0f);
            float pn = fn.x + fn.y + bn_half;   // both halves add bn/2
            pr += __shfl_xor_sync(0xffffffffu, pr, 1);
            pz += __shfl_xor_sync(0xffffffffu, pz, 1);
            pn += __shfl_xor_sync(0xffffffffu, pn, 1);

            const float R  = sigm_t(pr);
            const float Z  = sigm_t(pz);
            const float N  = tanha(fmaf(R, pn, b0));
            const float hn = fmaf(Z, hprev - N, N);     // (1-z)n + z h
            hprev = hn;
            if (half == 0) h_sh[cur ^ 1][k] = __float2half(hn);
            sum += hn;
            mx = fmaxf(mx, hn);

            __syncthreads();
        }
        q2 = qn0; q3 = qn1;
    }

    if (half == 0) {
        float* f = g_feats + b * 256;
        if (d == 0) { f[k]      = sum * (1.0f / T_LEN); f[128 + k] = mx; }
        else        { f[64 + k] = sum * (1.0f / T_LEN); f[192 + k] = mx; }
    }
}

// =====================================================================
// Kernel C v2 (FROZEN): classifier head, 256 threads per batch row.
// =====================================================================
__global__ void __launch_bounds__(256) kC(
    const float* __restrict__ w1, const float* __restrict__ b1,
    const float* __restrict__ w2, const float* __restrict__ b2,
    float* __restrict__ out)
{
    const int b   = blockIdx.x;
    const int tid = threadIdx.x;
    __shared__ float hid[64];

    {
        const int j = tid >> 2, q = tid & 3;
        const float4* f4 = (const float4*)(g_feats + b * 256 + q * 64);
        const float4* w4 = (const float4*)(w1 + j * 256 + q * 64);
        float a0 = 0.f, a1 = 0.f, a2 = 0.f, a3 = 0.f;
#pragma unroll
        for (int i = 0; i < 16; i += 4) {
            float4 fa = f4[i],     wa = w4[i];
            float4 fb = f4[i + 1], wb = w4[i + 1];
            float4 fc = f4[i + 2], wc = w4[i + 2];
            float4 fd = f4[i + 3], wd = w4[i + 3];
            a0 += fa.x * wa.x + fa.y * wa.y + fa.z * wa.z + fa.w * wa.w;
            a1 += fb.x * wb.x + fb.y * wb.y + fb.z * wb.z + fb.w * wb.w;
            a2 += fc.x * wc.x + fc.y * wc.y + fc.z * wc.z + fc.w * wc.w;
            a3 += fd.x * wd.x + fd.y * wd.y + fd.z * wd.z + fd.w * wd.w;
        }
        float acc = (a0 + a1) + (a2 + a3);
        acc += __shfl_xor_sync(0xffffffffu, acc, 1);
        acc += __shfl_xor_sync(0xffffffffu, acc, 2);
        if (q == 0) {
            acc += b1[j];
            hid[j] = 0.5f * acc * (1.0f + erff(acc * 0.70710678118654752f));
        }
    }
    __syncthreads();

    if (tid < NCLS * 8) {
        const int c = tid >> 3, i8 = tid & 7;
        const float* w2r = w2 + c * 64 + i8 * 8;
        const float* hp  = hid + i8 * 8;
        float o = 0.f;
#pragma unroll
        for (int i = 0; i < 8; i++) o += hp[i] * w2r[i];
        o += __shfl_xor_sync(0xffffffffu, o, 1);
        o += __shfl_xor_sync(0xffffffffu, o, 2);
        o += __shfl_xor_sync(0xffffffffu, o, 4);
        if (i8 == 0) out[b * NCLS + c] = o + b2[c];
    }
}

// =====================================================================
extern "C" void kernel_launch(void* const* d_in, const int* in_sizes, int n_in,
                              void* d_out, int out_size)
{
    const int*   tokens = (const int*)  d_in[0];
    const float* emb    = (const float*)d_in[1];
    const float* wih_f  = (const float*)d_in[2];
    const float* whh_f  = (const float*)d_in[3];
    const float* bih_f  = (const float*)d_in[4];
    const float* bhh_f  = (const float*)d_in[5];
    const float* wih_b  = (const float*)d_in[6];
    const float* whh_b  = (const float*)d_in[7];
    const float* bih_b  = (const float*)d_in[8];
    const float* bhh_b  = (const float*)d_in[9];
    const float* w1     = (const float*)d_in[10];
    const float* b1     = (const float*)d_in[11];
    const float* w2     = (const float*)d_in[12];
    const float* b2     = (const float*)d_in[13];
    float* out = (float*)d_out;

    kT<<<dim3(B_SZ, 2), 256>>>(tokens);
    const int vtiles = (VOCAB + 63) / 64;   // 786
    kA2<<<dim3(vtiles, 4), 256>>>(emb, wih_f, bih_f, bhh_f, wih_b, bih_b, bhh_b);
    kB<<<256, 128>>>(whh_f, bhh_f, whh_b, bhh_b);
    kC<<<128, 256>>>(w1, b1, w2, b2, out);
}